// round 16
// baseline (speedup 1.0000x reference)
#include <cuda_runtime.h>
#include <cuda_bf16.h>
#include <cstdint>

#define Bq 4
#define Hq 16
#define Sq 4096
#define Dq 64
#define BHq (Bq*Hq)            // 64

#define SPLIT1 8
#define CHUNK1 (Sq/SPLIT1)     // 512 s-rows per pass-1 block
#define NT1    8               // tiles of 64 s
#define NPART  SPLIT1

#define SPLIT3 8
#define CHUNK3 (Sq/SPLIT3)     // 512 rows per pass-3 block
#define TILE3  128
#define NT3    (CHUNK3/TILE3)  // 4

__device__ float g_part[NPART][BHq][Dq*Dq];
__device__ float g_k1p [SPLIT1][BHq][Dq];
__device__ float g_kvT[BHq][Dq*Dq];   // kv transposed: [e][d]
__device__ float g_k1 [BHq][Dq];

__device__ __forceinline__ float phif(float x) {
    return x > 0.f ? x + 1.f : __expf(x);
}
#define SCALE 0.3535533905932738f  // 1/sqrt(sqrt(64))

__device__ __forceinline__ uint32_t s2u(const void* p) {
    uint32_t a;
    asm("{ .reg .u64 t; cvta.to.shared.u64 t, %1; cvt.u32.u64 %0, t; }"
        : "=r"(a) : "l"(p));
    return a;
}
__device__ __forceinline__ void ldsm4(uint32_t r[4], uint32_t addr) {
    asm volatile("ldmatrix.sync.aligned.m8n8.x4.shared.b16 {%0,%1,%2,%3}, [%4];"
                 : "=r"(r[0]), "=r"(r[1]), "=r"(r[2]), "=r"(r[3]) : "r"(addr));
}
__device__ __forceinline__ void mma_tf32(float c[4], const uint32_t a[4],
                                         uint32_t b0, uint32_t b1) {
    asm volatile(
        "mma.sync.aligned.m16n8k8.row.col.f32.tf32.tf32.f32 "
        "{%0,%1,%2,%3}, {%4,%5,%6,%7}, {%8,%9}, {%0,%1,%2,%3};"
        : "+f"(c[0]), "+f"(c[1]), "+f"(c[2]), "+f"(c[3])
        : "r"(a[0]), "r"(a[1]), "r"(a[2]), "r"(a[3]), "r"(b0), "r"(b1));
}
__device__ __forceinline__ uint32_t f2tf(float x) {
    uint32_t r;
    asm("cvt.rna.tf32.f32 %0, %1;" : "=r"(r) : "f"(x));
    return r;
}

// All smem tiles: row stride 68 u32 words (272 B: 272%128==16 -> ldsm rows
// conflict-free). 16B-chunk index XOR'd with (row>>3)&1 at store; ldsm
// lane addresses apply the matching XOR (derivation verified per group).

// ---------------------------------------------------------------------------
// Pass 1 (tf32 MMA): kv[d][e] = sum_s phi_k[s][d] v[s][e].
// Staging writes TRANSPOSED tf32 tiles kT[d][s], vT[e][s] (64x64, swizzled).
// 8 warps: warp w -> m-tile (d) = w>>1 (16 rows), n-half (e) = w&1 (32 cols).
// 8 k-steps (k8) per 64-s tile, 8 tiles.
// ---------------------------------------------------------------------------
__global__ void __launch_bounds__(256)
k1_mma(const float* __restrict__ K, const float* __restrict__ V,
       const float* __restrict__ mask)
{
    __shared__ uint32_t kT[64*68];
    __shared__ uint32_t vT[64*68];
    __shared__ float k1b[8][68];

    const int t  = threadIdx.x;
    const int w  = t >> 5, l = t & 31;
    const int bh = blockIdx.x & (BHq - 1);
    const int sp = blockIdx.x >> 6;
    const int b  = bh >> 4;
    const int s0 = sp * CHUNK1;

    const int r  = t >> 2;          // staged s-row in tile (0..63)
    const int qc = t & 3;           // d-block (16 elems)

    const int mt = w >> 1, nh = w & 1;
    const uint32_t uKT = s2u(kT), uVT = s2u(vT);
    // ldsm addressing with swizzle-compensated 16B selector
    const uint32_t aRow  = 16 * mt + (l & 15);
    const uint32_t selA  = ((l >> 4) & 1) ^ ((l >> 3) & 1);
    const uint32_t aBase = uKT + aRow * 272 + selA * 16;
    const uint32_t bRow  = 32 * nh + (l & 7) + 8 * ((l >> 4) & 1);
    const uint32_t selB  = ((l >> 3) & 1) ^ ((l >> 4) & 1);
    const uint32_t bBase = uVT + bRow * 272 + selB * 16;

    float c[4][4];
#pragma unroll
    for (int i = 0; i < 4; i++)
#pragma unroll
        for (int j = 0; j < 4; j++) c[i][j] = 0.f;
    float k1loc[16];
#pragma unroll
    for (int i = 0; i < 16; i++) k1loc[i] = 0.f;

    const float* Kb = K + (size_t)bh * Sq * Dq;
    const float* Vb = V + (size_t)bh * Sq * Dq;
    const float* Mb = mask + (size_t)b * Sq;

#pragma unroll 1
    for (int it = 0; it < NT1; it++) {
        const int s = s0 + it * 64 + r;
        float4 kk4[4], vv4[4];
#pragma unroll
        for (int c4 = 0; c4 < 4; c4++) {
            kk4[c4] = *(const float4*)(Kb + (size_t)s * Dq + 16 * qc + 4 * c4);
            vv4[c4] = *(const float4*)(Vb + (size_t)s * Dq + 16 * qc + 4 * c4);
        }
        const float m = Mb[s];

        __syncthreads();   // previous tile's ldsm reads complete

        // transposed swizzled stores: element d -> row d, s-word r
#pragma unroll
        for (int c4 = 0; c4 < 4; c4++) {
            const float kv_[4] = {kk4[c4].x, kk4[c4].y, kk4[c4].z, kk4[c4].w};
            const float vv_[4] = {vv4[c4].x, vv4[c4].y, vv4[c4].z, vv4[c4].w};
#pragma unroll
            for (int j = 0; j < 4; j++) {
                const int d  = 16 * qc + 4 * c4 + j;
                const int xr = ((4 * c4 + j) >> 3) & 1;   // = (d>>3)&1
                const int wd = d * 68 + ((((r >> 2) ^ xr) << 2) | (r & 3));
                const float p = phif(kv_[j] * SCALE) * m;
                k1loc[4 * c4 + j] += p;
                kT[wd] = f2tf(p);
                vT[wd] = f2tf(vv_[j]);
            }
        }
        __syncthreads();

#pragma unroll
        for (int kk = 0; kk < 8; kk++) {
            uint32_t a[4];
            ldsm4(a, aBase + kk * 32);
#pragma unroll
            for (int np = 0; np < 2; np++) {
                uint32_t bb[4];
                ldsm4(bb, bBase + np * 16 * 272 + kk * 32);
                mma_tf32(c[2*np],   a, bb[0], bb[1]);
                mma_tf32(c[2*np+1], a, bb[2], bb[3]);
            }
        }
    }

    // epilogue: kv partial
    float* dst = &g_part[sp][bh][0];
    const int r0 = 16 * mt + (l >> 2), r1 = r0 + 8;
#pragma unroll
    for (int nt = 0; nt < 4; nt++) {
        const int e = 32 * nh + 8 * nt + 2 * (l & 3);
        *(float2*)&dst[r0 * 64 + e] = make_float2(c[nt][0], c[nt][1]);
        *(float2*)&dst[r1 * 64 + e] = make_float2(c[nt][2], c[nt][3]);
    }

    // deterministic k_one reduction: warp xor-reduce over same-qc lanes
#pragma unroll
    for (int ofs = 4; ofs <= 16; ofs <<= 1)
#pragma unroll
        for (int i = 0; i < 16; i++)
            k1loc[i] += __shfl_xor_sync(0xffffffffu, k1loc[i], ofs);
    if (l < 4) {
#pragma unroll
        for (int i = 0; i < 16; i++) k1b[w][16 * l + i] = k1loc[i];
    }
    __syncthreads();
    if (t < Dq) {
        float s = 0.f;
#pragma unroll
        for (int ww = 0; ww < 8; ww++) s += k1b[ww][t];
        g_k1p[sp][bh][t] = s;
    }
}

// ---------------------------------------------------------------------------
// Pass 2: reduce partials; emit kvT[e][d] + k_one.
// ---------------------------------------------------------------------------
__global__ void __launch_bounds__(256)
k2_reduce()
{
    __shared__ float kvs[Dq][Dq + 1];
    const int bh = blockIdx.x;
    const int t  = threadIdx.x;

    for (int idx = t; idx < Dq * Dq; idx += 256) {
        float s = 0.f;
#pragma unroll
        for (int p = 0; p < NPART; p++) s += g_part[p][bh][idx];
        kvs[idx >> 6][idx & 63] = s;
    }
    if (t < Dq) {
        float s = 0.f;
#pragma unroll
        for (int p = 0; p < SPLIT1; p++) s += g_k1p[p][bh][t];
        g_k1[bh][t] = s;
    }
    __syncthreads();
    for (int idx = t; idx < Dq * Dq; idx += 256) {
        g_kvT[bh][idx] = kvs[idx & 63][idx >> 6];
    }
}

// ---------------------------------------------------------------------------
// Pass 3 (tf32 MMA): out = phi_q.kv / (phi_q.k_one + 1e-8).
// A = phi_q [s][d] row-major (natural), B = kvT [e][d] n-major (natural).
// Single tf32 term. 8 warps, warp w = m-tile (16 rows), full n=64.
// ---------------------------------------------------------------------------
#define SM3_A  0
#define SM3_B  (SM3_A + TILE3*68*4)         // 34816
#define SM3_PN (SM3_B + Dq*68*4)            // 52224: pnorm[128][2] f32
#define SM3_K1 (SM3_PN + TILE3*2*4)         // 53248
#define SM3_SZ (SM3_K1 + 256)               // 53504

__global__ void __launch_bounds__(256)
k3_mma(const float* __restrict__ Q, const float* __restrict__ mask,
       float* __restrict__ out)
{
    extern __shared__ char sm3[];
    const uint32_t sb = s2u(sm3);

    const int t  = threadIdx.x;
    const int w  = t >> 5, l = t & 31;
    const int bh = blockIdx.x >> 3;
    const int sp = blockIdx.x & 7;
    const int b  = bh >> 4;
    const int s0 = sp * CHUNK3;

    uint32_t* A = (uint32_t*)(sm3 + SM3_A);
    uint32_t* Bm = (uint32_t*)(sm3 + SM3_B);
    float* PN = (float*)(sm3 + SM3_PN);
    float* K1 = (float*)(sm3 + SM3_K1);

    // ---- stage B (kvT tf32, swizzled) + k1, once per block ----
    if (t < 128) {
        const int r = t >> 1, hf = t & 1;   // e row, d half
        const float* src = &g_kvT[bh][r * 64 + hf * 32];
        const int xr = (r >> 3) & 1;
#pragma unroll
        for (int cc = 0; cc < 8; cc++) {
            const float4 v = *(const float4*)(src + 4 * cc);
            const int chunk = (8 * hf + cc) ^ xr;
            *(uint4*)&Bm[r * 68 + 4 * chunk] =
                make_uint4(f2tf(v.x), f2tf(v.y), f2tf(v.z), f2tf(v.w));
        }
    }
    if (t < Dq) K1[t] = g_k1[bh][t];

    const float* Qb = Q + (size_t)bh * Sq * Dq;
    const float* Mb = mask + (size_t)b * Sq;
    float*       Ob = out + (size_t)bh * Sq * Dq;

    const uint32_t aRow  = 16 * w + (l & 15);
    const uint32_t selA  = ((l >> 4) & 1) ^ ((l >> 3) & 1);
    const uint32_t aBase = sb + SM3_A + aRow * 272 + selA * 16;
    const uint32_t bRow  = (l & 7) + 8 * ((l >> 4) & 1);
    const uint32_t selB  = ((l >> 3) & 1) ^ ((l >> 4) & 1);
    const uint32_t bBase = sb + SM3_B + bRow * 272 + selB * 16;

#pragma unroll 1
    for (int it = 0; it < NT3; it++) {
        const int sbase = s0 + it * TILE3;

        __syncthreads();   // previous tile's reads complete

        // ---- stage A tile (phi_q tf32, swizzled) + norm partials ----
        {
            const int r = t >> 1, hf = t & 1;
            const int row = sbase + r;
            const float m = Mb[row];
            const float* Qr = Qb + (size_t)row * Dq + hf * 32;
            const int xr = (r >> 3) & 1;
            float ns = 0.f;
#pragma unroll
            for (int cc = 0; cc < 8; cc++) {
                const float4 q = *(const float4*)(Qr + 4 * cc);
                const float p0 = phif(q.x * SCALE) * m;
                const float p1 = phif(q.y * SCALE) * m;
                const float p2 = phif(q.z * SCALE) * m;
                const float p3 = phif(q.w * SCALE) * m;
                const int chunk = (8 * hf + cc) ^ xr;
                *(uint4*)&A[r * 68 + 4 * chunk] =
                    make_uint4(f2tf(p0), f2tf(p1), f2tf(p2), f2tf(p3));
                const float* kc = K1 + hf * 32 + 4 * cc;
                ns += p0 * kc[0] + p1 * kc[1] + p2 * kc[2] + p3 * kc[3];
            }
            PN[r * 2 + hf] = ns;
        }
        __syncthreads();

        // ---- MMA mainloop: 8 k-steps x 8 n8-tiles, single tf32 term ----
        float c[8][4];
#pragma unroll
        for (int j = 0; j < 8; j++)
#pragma unroll
            for (int i = 0; i < 4; i++) c[j][i] = 0.f;

#pragma unroll
        for (int kk = 0; kk < 8; kk++) {
            uint32_t a[4];
            ldsm4(a, aBase + kk * 32);
#pragma unroll
            for (int ntp = 0; ntp < 4; ntp++) {
                uint32_t bb[4];
                ldsm4(bb, bBase + ntp * 16 * 272 + kk * 32);
                mma_tf32(c[2*ntp],   a, bb[0], bb[1]);
                mma_tf32(c[2*ntp+1], a, bb[2], bb[3]);
            }
        }

        // ---- epilogue: normalize + store ----
        {
            const int r0 = 16 * w + (l >> 2);
            const int r1 = r0 + 8;
            const float inv0 = 1.0f / (PN[r0 * 2] + PN[r0 * 2 + 1] + 1e-8f);
            const float inv1 = 1.0f / (PN[r1 * 2] + PN[r1 * 2 + 1] + 1e-8f);
            float* O0 = Ob + (size_t)(sbase + r0) * Dq + 2 * (l & 3);
            float* O1 = Ob + (size_t)(sbase + r1) * Dq + 2 * (l & 3);
#pragma unroll
            for (int j = 0; j < 8; j++) {
                *(float2*)(O0 + 8 * j) = make_float2(c[j][0] * inv0, c[j][1] * inv0);
                *(float2*)(O1 + 8 * j) = make_float2(c[j][2] * inv1, c[j][3] * inv1);
            }
        }
    }
}

// ---------------------------------------------------------------------------
extern "C" void kernel_launch(void* const* d_in, const int* in_sizes, int n_in,
                              void* d_out, int out_size)
{
    (void)in_sizes; (void)n_in; (void)out_size;
    const float* Q = (const float*)d_in[0];
    const float* K = (const float*)d_in[1];
    const float* V = (const float*)d_in[2];
    const float* M = (const float*)d_in[3];
    float* O = (float*)d_out;

    cudaFuncSetAttribute(k3_mma, cudaFuncAttributeMaxDynamicSharedMemorySize, SM3_SZ);

    k1_mma   <<<BHq * SPLIT1, 256>>>(K, V, M);
    k2_reduce<<<BHq,          256>>>();
    k3_mma   <<<BHq * SPLIT3, 256, SM3_SZ>>>(Q, M, O);
}

// round 17
// speedup vs baseline: 1.0008x; 1.0008x over previous
#include <cuda_runtime.h>
#include <cuda_bf16.h>
#include <cstdint>

#define Bq 4
#define Hq 16
#define Sq 4096
#define Dq 64
#define BHq (Bq*Hq)            // 64

#define SPLIT1 8
#define CHUNK1 (Sq/SPLIT1)     // 512 s-rows per pass-1 block
#define NT1    8               // tiles of 64 s
#define NPART  SPLIT1

#define SPLIT3 8
#define CHUNK3 (Sq/SPLIT3)     // 512 rows per pass-3 block
#define TILE3  128
#define NT3    (CHUNK3/TILE3)  // 4

__device__ float g_part[NPART][BHq][Dq*Dq];
__device__ float g_k1p [SPLIT1][BHq][Dq];
__device__ float g_kvT[BHq][Dq*Dq];   // kv transposed: [e][d]
__device__ float g_k1 [BHq][Dq];

__device__ __forceinline__ float phif(float x) {
    return x > 0.f ? x + 1.f : __expf(x);
}
#define SCALE 0.3535533905932738f  // 1/sqrt(sqrt(64))

__device__ __forceinline__ uint32_t s2u(const void* p) {
    uint32_t a;
    asm("{ .reg .u64 t; cvta.to.shared.u64 t, %1; cvt.u32.u64 %0, t; }"
        : "=r"(a) : "l"(p));
    return a;
}
__device__ __forceinline__ void ldsm4(uint32_t r[4], uint32_t addr) {
    asm volatile("ldmatrix.sync.aligned.m8n8.x4.shared.b16 {%0,%1,%2,%3}, [%4];"
                 : "=r"(r[0]), "=r"(r[1]), "=r"(r[2]), "=r"(r[3]) : "r"(addr));
}
__device__ __forceinline__ void mma_tf32(float c[4], const uint32_t a[4],
                                         uint32_t b0, uint32_t b1) {
    asm volatile(
        "mma.sync.aligned.m16n8k8.row.col.f32.tf32.tf32.f32 "
        "{%0,%1,%2,%3}, {%4,%5,%6,%7}, {%8,%9}, {%0,%1,%2,%3};"
        : "+f"(c[0]), "+f"(c[1]), "+f"(c[2]), "+f"(c[3])
        : "r"(a[0]), "r"(a[1]), "r"(a[2]), "r"(a[3]), "r"(b0), "r"(b1));
}
__device__ __forceinline__ uint32_t f2tf(float x) {
    uint32_t r;
    asm("cvt.rna.tf32.f32 %0, %1;" : "=r"(r) : "f"(x));
    return r;
}

// All smem tiles: row stride 68 u32 words (272 B: 272%128==16 -> ldsm rows
// conflict-free). 16B-chunk index XOR'd with (row>>3)&1 at store; ldsm
// lane addresses apply the matching XOR (derivation verified per group).

// ---------------------------------------------------------------------------
// Pass 1 (tf32 MMA): kv[d][e] = sum_s phi_k[s][d] v[s][e].
// Staging writes TRANSPOSED tf32 tiles kT[d][s], vT[e][s] (64x64, swizzled).
// 8 warps: warp w -> m-tile (d) = w>>1 (16 rows), n-half (e) = w&1 (32 cols).
// 8 k-steps (k8) per 64-s tile, 8 tiles.
// ---------------------------------------------------------------------------
__global__ void __launch_bounds__(256)
k1_mma(const float* __restrict__ K, const float* __restrict__ V,
       const float* __restrict__ mask)
{
    __shared__ uint32_t kT[64*68];
    __shared__ uint32_t vT[64*68];
    __shared__ float k1b[8][68];

    const int t  = threadIdx.x;
    const int w  = t >> 5, l = t & 31;
    const int bh = blockIdx.x & (BHq - 1);
    const int sp = blockIdx.x >> 6;
    const int b  = bh >> 4;
    const int s0 = sp * CHUNK1;

    const int r  = t >> 2;          // staged s-row in tile (0..63)
    const int qc = t & 3;           // d-block (16 elems)

    const int mt = w >> 1, nh = w & 1;
    const uint32_t uKT = s2u(kT), uVT = s2u(vT);
    // ldsm addressing with swizzle-compensated 16B selector
    const uint32_t aRow  = 16 * mt + (l & 15);
    const uint32_t selA  = ((l >> 4) & 1) ^ ((l >> 3) & 1);
    const uint32_t aBase = uKT + aRow * 272 + selA * 16;
    const uint32_t bRow  = 32 * nh + (l & 7) + 8 * ((l >> 4) & 1);
    const uint32_t selB  = ((l >> 3) & 1) ^ ((l >> 4) & 1);
    const uint32_t bBase = uVT + bRow * 272 + selB * 16;

    float c[4][4];
#pragma unroll
    for (int i = 0; i < 4; i++)
#pragma unroll
        for (int j = 0; j < 4; j++) c[i][j] = 0.f;
    float k1loc[16];
#pragma unroll
    for (int i = 0; i < 16; i++) k1loc[i] = 0.f;

    const float* Kb = K + (size_t)bh * Sq * Dq;
    const float* Vb = V + (size_t)bh * Sq * Dq;
    const float* Mb = mask + (size_t)b * Sq;

#pragma unroll 1
    for (int it = 0; it < NT1; it++) {
        const int s = s0 + it * 64 + r;
        float4 kk4[4], vv4[4];
#pragma unroll
        for (int c4 = 0; c4 < 4; c4++) {
            kk4[c4] = *(const float4*)(Kb + (size_t)s * Dq + 16 * qc + 4 * c4);
            vv4[c4] = *(const float4*)(Vb + (size_t)s * Dq + 16 * qc + 4 * c4);
        }
        const float m = Mb[s];

        __syncthreads();   // previous tile's ldsm reads complete

        // transposed swizzled stores: element d -> row d, s-word r
#pragma unroll
        for (int c4 = 0; c4 < 4; c4++) {
            const float kv_[4] = {kk4[c4].x, kk4[c4].y, kk4[c4].z, kk4[c4].w};
            const float vv_[4] = {vv4[c4].x, vv4[c4].y, vv4[c4].z, vv4[c4].w};
#pragma unroll
            for (int j = 0; j < 4; j++) {
                const int d  = 16 * qc + 4 * c4 + j;
                const int xr = ((4 * c4 + j) >> 3) & 1;   // = (d>>3)&1
                const int wd = d * 68 + ((((r >> 2) ^ xr) << 2) | (r & 3));
                const float p = phif(kv_[j] * SCALE) * m;
                k1loc[4 * c4 + j] += p;
                kT[wd] = f2tf(p);
                vT[wd] = f2tf(vv_[j]);
            }
        }
        __syncthreads();

#pragma unroll
        for (int kk = 0; kk < 8; kk++) {
            uint32_t a[4];
            ldsm4(a, aBase + kk * 32);
#pragma unroll
            for (int np = 0; np < 2; np++) {
                uint32_t bb[4];
                ldsm4(bb, bBase + np * 16 * 272 + kk * 32);
                mma_tf32(c[2*np],   a, bb[0], bb[1]);
                mma_tf32(c[2*np+1], a, bb[2], bb[3]);
            }
        }
    }

    // epilogue: kv partial
    float* dst = &g_part[sp][bh][0];
    const int r0 = 16 * mt + (l >> 2), r1 = r0 + 8;
#pragma unroll
    for (int nt = 0; nt < 4; nt++) {
        const int e = 32 * nh + 8 * nt + 2 * (l & 3);
        *(float2*)&dst[r0 * 64 + e] = make_float2(c[nt][0], c[nt][1]);
        *(float2*)&dst[r1 * 64 + e] = make_float2(c[nt][2], c[nt][3]);
    }

    // deterministic k_one reduction: warp xor-reduce over same-qc lanes
#pragma unroll
    for (int ofs = 4; ofs <= 16; ofs <<= 1)
#pragma unroll
        for (int i = 0; i < 16; i++)
            k1loc[i] += __shfl_xor_sync(0xffffffffu, k1loc[i], ofs);
    if (l < 4) {
#pragma unroll
        for (int i = 0; i < 16; i++) k1b[w][16 * l + i] = k1loc[i];
    }
    __syncthreads();
    if (t < Dq) {
        float s = 0.f;
#pragma unroll
        for (int ww = 0; ww < 8; ww++) s += k1b[ww][t];
        g_k1p[sp][bh][t] = s;
    }
}

// ---------------------------------------------------------------------------
// Pass 2: reduce partials; emit kvT[e][d] + k_one.
// ---------------------------------------------------------------------------
__global__ void __launch_bounds__(256)
k2_reduce()
{
    __shared__ float kvs[Dq][Dq + 1];
    const int bh = blockIdx.x;
    const int t  = threadIdx.x;

    for (int idx = t; idx < Dq * Dq; idx += 256) {
        float s = 0.f;
#pragma unroll
        for (int p = 0; p < NPART; p++) s += g_part[p][bh][idx];
        kvs[idx >> 6][idx & 63] = s;
    }
    if (t < Dq) {
        float s = 0.f;
#pragma unroll
        for (int p = 0; p < SPLIT1; p++) s += g_k1p[p][bh][t];
        g_k1[bh][t] = s;
    }
    __syncthreads();
    for (int idx = t; idx < Dq * Dq; idx += 256) {
        g_kvT[bh][idx] = kvs[idx & 63][idx >> 6];
    }
}

// ---------------------------------------------------------------------------
// Pass 3 (tf32 MMA): out = phi_q.kv / (phi_q.k_one + 1e-8).
// A = phi_q [s][d] row-major (natural), B = kvT [e][d] n-major (natural).
// Single tf32 term. 8 warps, warp w = m-tile (16 rows), full n=64.
// ---------------------------------------------------------------------------
#define SM3_A  0
#define SM3_B  (SM3_A + TILE3*68*4)         // 34816
#define SM3_PN (SM3_B + Dq*68*4)            // 52224: pnorm[128][2] f32
#define SM3_K1 (SM3_PN + TILE3*2*4)         // 53248
#define SM3_SZ (SM3_K1 + 256)               // 53504

__global__ void __launch_bounds__(256)
k3_mma(const float* __restrict__ Q, const float* __restrict__ mask,
       float* __restrict__ out)
{
    extern __shared__ char sm3[];
    const uint32_t sb = s2u(sm3);

    const int t  = threadIdx.x;
    const int w  = t >> 5, l = t & 31;
    const int bh = blockIdx.x >> 3;
    const int sp = blockIdx.x & 7;
    const int b  = bh >> 4;
    const int s0 = sp * CHUNK3;

    uint32_t* A = (uint32_t*)(sm3 + SM3_A);
    uint32_t* Bm = (uint32_t*)(sm3 + SM3_B);
    float* PN = (float*)(sm3 + SM3_PN);
    float* K1 = (float*)(sm3 + SM3_K1);

    // ---- stage B (kvT tf32, swizzled) + k1, once per block ----
    if (t < 128) {
        const int r = t >> 1, hf = t & 1;   // e row, d half
        const float* src = &g_kvT[bh][r * 64 + hf * 32];
        const int xr = (r >> 3) & 1;
#pragma unroll
        for (int cc = 0; cc < 8; cc++) {
            const float4 v = *(const float4*)(src + 4 * cc);
            const int chunk = (8 * hf + cc) ^ xr;
            *(uint4*)&Bm[r * 68 + 4 * chunk] =
                make_uint4(f2tf(v.x), f2tf(v.y), f2tf(v.z), f2tf(v.w));
        }
    }
    if (t < Dq) K1[t] = g_k1[bh][t];

    const float* Qb = Q + (size_t)bh * Sq * Dq;
    const float* Mb = mask + (size_t)b * Sq;
    float*       Ob = out + (size_t)bh * Sq * Dq;

    const uint32_t aRow  = 16 * w + (l & 15);
    const uint32_t selA  = ((l >> 4) & 1) ^ ((l >> 3) & 1);
    const uint32_t aBase = sb + SM3_A + aRow * 272 + selA * 16;
    const uint32_t bRow  = (l & 7) + 8 * ((l >> 4) & 1);
    const uint32_t selB  = ((l >> 3) & 1) ^ ((l >> 4) & 1);
    const uint32_t bBase = sb + SM3_B + bRow * 272 + selB * 16;

#pragma unroll 1
    for (int it = 0; it < NT3; it++) {
        const int sbase = s0 + it * TILE3;

        __syncthreads();   // previous tile's reads complete

        // ---- stage A tile (phi_q tf32, swizzled) + norm partials ----
        {
            const int r = t >> 1, hf = t & 1;
            const int row = sbase + r;
            const float m = Mb[row];
            const float* Qr = Qb + (size_t)row * Dq + hf * 32;
            const int xr = (r >> 3) & 1;
            float ns = 0.f;
#pragma unroll
            for (int cc = 0; cc < 8; cc++) {
                const float4 q = *(const float4*)(Qr + 4 * cc);
                const float p0 = phif(q.x * SCALE) * m;
                const float p1 = phif(q.y * SCALE) * m;
                const float p2 = phif(q.z * SCALE) * m;
                const float p3 = phif(q.w * SCALE) * m;
                const int chunk = (8 * hf + cc) ^ xr;
                *(uint4*)&A[r * 68 + 4 * chunk] =
                    make_uint4(f2tf(p0), f2tf(p1), f2tf(p2), f2tf(p3));
                const float* kc = K1 + hf * 32 + 4 * cc;
                ns += p0 * kc[0] + p1 * kc[1] + p2 * kc[2] + p3 * kc[3];
            }
            PN[r * 2 + hf] = ns;
        }
        __syncthreads();

        // ---- MMA mainloop: 8 k-steps x 8 n8-tiles, single tf32 term ----
        float c[8][4];
#pragma unroll
        for (int j = 0; j < 8; j++)
#pragma unroll
            for (int i = 0; i < 4; i++) c[j][i] = 0.f;

#pragma unroll
        for (int kk = 0; kk < 8; kk++) {
            uint32_t a[4];
            ldsm4(a, aBase + kk * 32);
#pragma unroll
            for (int ntp = 0; ntp < 4; ntp++) {
                uint32_t bb[4];
                ldsm4(bb, bBase + ntp * 16 * 272 + kk * 32);
                mma_tf32(c[2*ntp],   a, bb[0], bb[1]);
                mma_tf32(c[2*ntp+1], a, bb[2], bb[3]);
            }
        }

        // ---- epilogue: normalize + store ----
        {
            const int r0 = 16 * w + (l >> 2);
            const int r1 = r0 + 8;
            const float inv0 = 1.0f / (PN[r0 * 2] + PN[r0 * 2 + 1] + 1e-8f);
            const float inv1 = 1.0f / (PN[r1 * 2] + PN[r1 * 2 + 1] + 1e-8f);
            float* O0 = Ob + (size_t)(sbase + r0) * Dq + 2 * (l & 3);
            float* O1 = Ob + (size_t)(sbase + r1) * Dq + 2 * (l & 3);
#pragma unroll
            for (int j = 0; j < 8; j++) {
                *(float2*)(O0 + 8 * j) = make_float2(c[j][0] * inv0, c[j][1] * inv0);
                *(float2*)(O1 + 8 * j) = make_float2(c[j][2] * inv1, c[j][3] * inv1);
            }
        }
    }
}

// ---------------------------------------------------------------------------
extern "C" void kernel_launch(void* const* d_in, const int* in_sizes, int n_in,
                              void* d_out, int out_size)
{
    (void)in_sizes; (void)n_in; (void)out_size;
    const float* Q = (const float*)d_in[0];
    const float* K = (const float*)d_in[1];
    const float* V = (const float*)d_in[2];
    const float* M = (const float*)d_in[3];
    float* O = (float*)d_out;

    cudaFuncSetAttribute(k3_mma, cudaFuncAttributeMaxDynamicSharedMemorySize, SM3_SZ);

    k1_mma   <<<BHq * SPLIT1, 256>>>(K, V, M);
    k2_reduce<<<BHq,          256>>>();
    k3_mma   <<<BHq * SPLIT3, 256, SM3_SZ>>>(Q, M, O);
}